// round 15
// baseline (speedup 1.0000x reference)
#include <cuda_runtime.h>
#include <cstdint>

// SplitMLP: persistent double-buffered cp.async pipeline + mma.sync tf32.
// 444 persistent CTAs x 256 threads (3 CTAs/SM); CTA c handles groups
// c, c+444, ... Per group: D[128,64] = [day|items_g][128x48] * W1[64x48]^T,
// bias+ReLU in fragments, fc2 (O=4) via quad shfl reduction.
// SMEM tiles use XOR-chunk swizzle (chunk q of row r stored at q^(r&7),
// stride-32-float rows) -> conflict-free fragment gathers, no padding.

#define CC 16
#define VV 32
#define HH 64
#define OO 4
#define GG 10000
#define NB 444
#define NT 256

// float-index SMEM layout
#define DAY_OFF   0        // 128 x 16 (stride 16, swizzle &3)
#define BUF0_OFF  2048
#define BUF_FLOATS 7552
#define ITEMS_OFF 0        // 128 x 32 (stride 32, swizzle &7)
#define W1V_OFF   4096     // 64 x 32  (stride 32, swizzle &7)
#define W1D_OFF   6144     // 64 x 16  (stride 16, swizzle &3)
#define W2_OFF    7168     // 256
#define B1_OFF    7424     // 64
#define B2_OFF    7488     // 4
#define SMEM_FLOATS (BUF0_OFF + 2 * BUF_FLOATS)   // 17152
#define SMEM_BYTES  (SMEM_FLOATS * 4)             // 68608

__device__ __forceinline__ void cpa16(uint32_t dst, const void* src) {
    asm volatile("cp.async.ca.shared.global [%0], [%1], 16;"
                 :: "r"(dst), "l"(__cvta_generic_to_global(src)));
}
__device__ __forceinline__ void cpa_commit() {
    asm volatile("cp.async.commit_group;");
}
template <int N>
__device__ __forceinline__ void cpa_wait() {
    asm volatile("cp.async.wait_group %0;" :: "n"(N));
}

__device__ __forceinline__ void mma_t(float* d, const uint32_t* a,
                                      const uint32_t* b) {
    asm volatile(
        "mma.sync.aligned.m16n8k8.row.col.f32.tf32.tf32.f32 "
        "{%0,%1,%2,%3}, {%4,%5,%6,%7}, {%8,%9}, {%0,%1,%2,%3};"
        : "+f"(d[0]), "+f"(d[1]), "+f"(d[2]), "+f"(d[3])
        : "r"(a[0]), "r"(a[1]), "r"(a[2]), "r"(a[3]), "r"(b[0]), "r"(b[1]));
}

// swizzled float-index: stride-32 rows (8 chunks), mask 7
__device__ __forceinline__ int sw8(int base, int row, int chunk) {
    return base + row * 32 + ((chunk ^ (row & 7)) << 2);
}
// stride-16 rows (4 chunks), mask 3
__device__ __forceinline__ int sw4(int base, int row, int chunk) {
    return base + row * 16 + ((chunk ^ (row & 3)) << 2);
}

__global__ __launch_bounds__(NT) void splitmlp_kernel(
    const float* __restrict__ day,     // (B, C)
    const float* __restrict__ items,   // (B, G, V)
    const float* __restrict__ W1_day,  // (G, H, C)
    const float* __restrict__ W1_var,  // (G, H, V)
    const float* __restrict__ b1,      // (G, H)
    const float* __restrict__ W2,      // (G, O, H)
    const float* __restrict__ b2,      // (G, O)
    float* __restrict__ out)           // (B, G, O)
{
    extern __shared__ float smf[];
    const uint32_t sb = (uint32_t)__cvta_generic_to_shared(smf);
    const uint32_t* const smu = (const uint32_t*)smf;

    const int tid  = threadIdx.x;
    const int lane = tid & 31;
    const int wid  = tid >> 5;      // 0..7
    const int gid  = lane >> 2;
    const int tig  = lane & 3;
    const int m0   = wid * 16;      // warp's 16-row tile

    // ---- stage one group into buffer `buf` ----
    auto stage = [&](int buf, int g) {
        const int bofl = BUF0_OFF + buf * BUF_FLOATS;
        // items[:, g, :]: 1024 chunks of 16B
        #pragma unroll
        for (int ch = tid; ch < 1024; ch += NT) {
            int b = ch >> 3, q = ch & 7;
            cpa16(sb + sw8(bofl + ITEMS_OFF, b, q) * 4u,
                  items + ((size_t)b * GG + g) * VV + q * 4);
        }
        // W1_var(g): 512 chunks
        #pragma unroll
        for (int ch = tid; ch < 512; ch += NT) {
            int j = ch >> 3, q = ch & 7;
            cpa16(sb + sw8(bofl + W1V_OFF, j, q) * 4u,
                  W1_var + ((size_t)g * HH + j) * VV + q * 4);
        }
        // W1_day(g): 256 chunks
        {
            int j = tid >> 2, q = tid & 3;
            cpa16(sb + sw4(bofl + W1D_OFF, j, q) * 4u,
                  W1_day + ((size_t)g * HH + j) * CC + q * 4);
        }
        // W2 / b1 / b2
        if (tid < 64)
            cpa16(sb + (bofl + W2_OFF + tid * 4) * 4u,
                  W2 + (size_t)g * 256 + tid * 4);
        else if (tid < 80)
            cpa16(sb + (bofl + B1_OFF + (tid - 64) * 4) * 4u,
                  b1 + (size_t)g * HH + (tid - 64) * 4);
        else if (tid == 80)
            cpa16(sb + (bofl + B2_OFF) * 4u, b2 + (size_t)g * OO);
    };

    // ---- prologue ----
    const int g0 = blockIdx.x;
    if (g0 < GG) stage(0, g0);
    cpa_commit();
    {   // day (group-invariant), swizzled stores
        const float4* p = (const float4*)day;
        #pragma unroll
        for (int i = tid; i < 512; i += NT) {
            int b = i >> 2, q = i & 3;
            *(float4*)&smf[sw4(DAY_OFF, b, q)] = p[i];
        }
    }

    int buf = 0;
    for (int g = g0; g < GG; g += NB) {
        const int gn = g + NB;
        if (gn < GG) stage(buf ^ 1, gn);
        cpa_commit();
        cpa_wait<1>();
        __syncthreads();

        const int bofl = BUF0_OFF + buf * BUF_FLOATS;
        const float* sb1 = smf + bofl + B1_OFF;
        const float* sb2 = smf + bofl + B2_OFF;
        const float* sw2 = smf + bofl + W2_OFF;

        // ---- fc1 GEMM: warp owns rows [m0, m0+16) ----
        float acc[8][4];
        #pragma unroll
        for (int n8 = 0; n8 < 8; ++n8)
            #pragma unroll
            for (int q = 0; q < 4; ++q) acc[n8][q] = 0.0f;

        const int r0 = m0 + gid, r1 = r0 + 8;

        #pragma unroll
        for (int kt = 0; kt < 6; ++kt) {
            uint32_t af[4];
            if (kt < 2) {
                const int c0 = kt * 2;
                af[0] = smu[sw4(DAY_OFF, r0, c0) + tig];
                af[1] = smu[sw4(DAY_OFF, r1, c0) + tig];
                af[2] = smu[sw4(DAY_OFF, r0, c0 + 1) + tig];
                af[3] = smu[sw4(DAY_OFF, r1, c0 + 1) + tig];
                #pragma unroll
                for (int n8 = 0; n8 < 8; ++n8) {
                    int n = n8 * 8 + gid;
                    uint32_t bf[2];
                    bf[0] = smu[sw4(bofl + W1D_OFF, n, c0) + tig];
                    bf[1] = smu[sw4(bofl + W1D_OFF, n, c0 + 1) + tig];
                    mma_t(acc[n8], af, bf);
                }
            } else {
                const int c0 = (kt - 2) * 2;
                af[0] = smu[sw8(bofl + ITEMS_OFF, r0, c0) + tig];
                af[1] = smu[sw8(bofl + ITEMS_OFF, r1, c0) + tig];
                af[2] = smu[sw8(bofl + ITEMS_OFF, r0, c0 + 1) + tig];
                af[3] = smu[sw8(bofl + ITEMS_OFF, r1, c0 + 1) + tig];
                #pragma unroll
                for (int n8 = 0; n8 < 8; ++n8) {
                    int n = n8 * 8 + gid;
                    uint32_t bf[2];
                    bf[0] = smu[sw8(bofl + W1V_OFF, n, c0) + tig];
                    bf[1] = smu[sw8(bofl + W1V_OFF, n, c0 + 1) + tig];
                    mma_t(acc[n8], af, bf);
                }
            }
        }

        // ---- bias + ReLU in fragments ----
        // acc[n8][2*s+d] -> row = m0+8s+gid, col = 8*n8+2*tig+d
        #pragma unroll
        for (int n8 = 0; n8 < 8; ++n8) {
            float2 bv = *(const float2*)&sb1[8 * n8 + 2 * tig];
            acc[n8][0] = fmaxf(acc[n8][0] + bv.x, 0.0f);
            acc[n8][1] = fmaxf(acc[n8][1] + bv.y, 0.0f);
            acc[n8][2] = fmaxf(acc[n8][2] + bv.x, 0.0f);
            acc[n8][3] = fmaxf(acc[n8][3] + bv.y, 0.0f);
        }

        // ---- fc2: per-thread partials, quad reduce ----
        float res[2][OO];
        #pragma unroll
        for (int s = 0; s < 2; ++s)
            #pragma unroll
            for (int o = 0; o < OO; ++o) res[s][o] = 0.0f;

        #pragma unroll
        for (int o = 0; o < OO; ++o) {
            #pragma unroll
            for (int n8 = 0; n8 < 8; ++n8) {
                float2 wv = *(const float2*)&sw2[o * HH + 8 * n8 + 2 * tig];
                res[0][o] = fmaf(acc[n8][0], wv.x,
                            fmaf(acc[n8][1], wv.y, res[0][o]));
                res[1][o] = fmaf(acc[n8][2], wv.x,
                            fmaf(acc[n8][3], wv.y, res[1][o]));
            }
        }

        #pragma unroll
        for (int s = 0; s < 2; ++s)
            #pragma unroll
            for (int o = 0; o < OO; ++o) {
                float v = res[s][o];
                v += __shfl_xor_sync(0xffffffffu, v, 1);
                v += __shfl_xor_sync(0xffffffffu, v, 2);
                res[s][o] = v;
            }

        if (tig == 0) {
            float4* outp = (float4*)out;
            float4 bias2 = { sb2[0], sb2[1], sb2[2], sb2[3] };
            #pragma unroll
            for (int s = 0; s < 2; ++s) {
                int row = m0 + 8 * s + gid;
                float4 o4;
                o4.x = res[s][0] + bias2.x;
                o4.y = res[s][1] + bias2.y;
                o4.z = res[s][2] + bias2.z;
                o4.w = res[s][3] + bias2.w;
                outp[(size_t)row * GG + g] = o4;
            }
        }

        __syncthreads();   // all reads of buf done before it is restaged
        buf ^= 1;
    }
}

extern "C" void kernel_launch(void* const* d_in, const int* in_sizes, int n_in,
                              void* d_out, int out_size) {
    const float* day    = (const float*)d_in[0];
    const float* items  = (const float*)d_in[1];
    const float* W1_day = (const float*)d_in[2];
    const float* W1_var = (const float*)d_in[3];
    const float* b1     = (const float*)d_in[4];
    const float* W2     = (const float*)d_in[5];
    const float* b2     = (const float*)d_in[6];
    float* out = (float*)d_out;

    cudaFuncSetAttribute(splitmlp_kernel,
                         cudaFuncAttributeMaxDynamicSharedMemorySize,
                         SMEM_BYTES);
    splitmlp_kernel<<<NB, NT, SMEM_BYTES>>>(day, items, W1_day, W1_var, b1,
                                            W2, b2, out);
}